// round 15
// baseline (speedup 1.0000x reference)
#include <cuda_runtime.h>
#include <cuda_fp16.h>
#include <cstdint>

// ---------------------------------------------------------------------------
// R10: exact R8 structure (H1/H2 via smem, 492us measured) + ONLY the 1-MUFU
//      softplus (log1p via deg-6 poly; <=6.5e-5 abs). The R9 register-resident
//      A-fragment change is reverted: it pushed peak liveness past the
//      128-reg cap (spills) and regressed to 518us.
// ---------------------------------------------------------------------------

namespace {
constexpr int NNODES = 20000;
constexpr int NEDGES = 640000;
constexpr int H      = 128;
constexpr int ETILE  = 256;
constexpr int NTILES = NEDGES / ETILE;   // 2500

// ---- edge smem layout ----
constexpr int OW_E1  = 0;
constexpr int OW_V1  = 32768;
constexpr int OW_E2  = 65536;
constexpr int OW_E3  = 98304;
constexpr int OWX_E1 = 131072;
constexpr int OWX_V1 = 135168;
constexpr int OACTA  = 139264;   // 256 rows x 256 B
constexpr int OACTX  = 204800;   // 256 rows x 48 B
constexpr int O_BE1  = 217088;
constexpr int O_GE1  = 217600;
constexpr int O_BTE1 = 218112;
constexpr int O_BV1  = 218624;
constexpr int O_GV1  = 219136;
constexpr int O_BTV1 = 219648;
constexpr int O_WV2  = 220160;
constexpr int O_BE2  = 220672;
constexpr int O_BE3  = 221184;
constexpr int O_REL  = 221696;
constexpr int O_DST  = 223744;
constexpr int O_BV2  = 224768;
constexpr int EDGE_SMEM = 224896;

// ---- node smem layout ----
constexpr int ON_A1   = 0;
constexpr int ON_A2   = 65536;
constexpr int ON_W1a  = 131072;
constexpr int ON_W1b  = 163840;
constexpr int ON_W2   = 196608;
constexpr int ON_BH1  = 229376;
constexpr int ON_GH1  = 229888;
constexpr int ON_BTH1 = 230400;
constexpr int ON_BH2  = 230912;
constexpr int ON_RDEN = 231168;
constexpr int NODE_SMEM = 232192;
constexpr int NODE_CTAS = (NNODES + 255) / 256;  // 79
}  // namespace

__device__ __align__(16) float g_mh[NNODES * H];
__device__ __align__(16) float g_mv[NNODES * 2];
__device__ float g_cnt[NNODES];

struct EdgeParams {
  const float *x, *pos, *vel;
  const float *We1, *be1, *ge1, *bte1, *We2, *be2, *We3, *be3;
  const float *Wv1, *bv1, *gv1, *btv1, *Wv2, *bv2;
  const int   *ei;
};
struct NodeParams {
  const float *x;
  const float *Wh1, *bh1, *gh1, *bth1, *Wh2, *bh2;
  float       *out;
};

// ------------------------------- helpers -----------------------------------
__device__ __forceinline__ uint32_t smem_u32(const void* p) {
  uint32_t a;
  asm("{ .reg .u64 t; cvta.to.shared.u64 t, %1; cvt.u32.u64 %0, t; }"
      : "=r"(a) : "l"(p));
  return a;
}
__device__ __forceinline__ void ldsm4(uint32_t& a0, uint32_t& a1, uint32_t& a2,
                                      uint32_t& a3, uint32_t addr) {
  asm volatile(
      "ldmatrix.sync.aligned.m8n8.x4.shared.b16 {%0,%1,%2,%3}, [%4];"
      : "=r"(a0), "=r"(a1), "=r"(a2), "=r"(a3) : "r"(addr));
}
__device__ __forceinline__ void ldsm4t(uint32_t& a0, uint32_t& a1, uint32_t& a2,
                                       uint32_t& a3, uint32_t addr) {
  asm volatile(
      "ldmatrix.sync.aligned.m8n8.x4.trans.shared.b16 {%0,%1,%2,%3}, [%4];"
      : "=r"(a0), "=r"(a1), "=r"(a2), "=r"(a3) : "r"(addr));
}
__device__ __forceinline__ void mma16816(float* c, uint32_t a0, uint32_t a1,
                                         uint32_t a2, uint32_t a3, uint32_t b0,
                                         uint32_t b1) {
  asm volatile(
      "mma.sync.aligned.m16n8k16.row.col.f32.f16.f16.f32 "
      "{%0,%1,%2,%3}, {%4,%5,%6,%7}, {%8,%9}, {%0,%1,%2,%3};"
      : "+f"(c[0]), "+f"(c[1]), "+f"(c[2]), "+f"(c[3])
      : "r"(a0), "r"(a1), "r"(a2), "r"(a3), "r"(b0), "r"(b1));
}
__device__ __forceinline__ void red4(float* p, float a, float b, float c,
                                     float d) {
  asm volatile("red.global.add.v4.f32 [%0], {%1,%2,%3,%4};"
               :: "l"(p), "f"(a), "f"(b), "f"(c), "f"(d) : "memory");
}
__device__ __forceinline__ void red2(float* p, float a, float b) {
  asm volatile("red.global.add.v2.f32 [%0], {%1,%2};"
               :: "l"(p), "f"(a), "f"(b) : "memory");
}
__device__ __forceinline__ uint32_t swb(int row, int col) {
  return (uint32_t)row * 256u + (uint32_t)((((col >> 3) ^ (row & 7)) & 15) << 4) +
         (uint32_t)((col & 7) << 1);
}
__device__ __forceinline__ uint32_t h2pack(float a, float b) {
  __half2 h = __floats2half2_rn(a, b);
  return (uint32_t)__half_as_ushort(__low2half(h)) |
         ((uint32_t)__half_as_ushort(__high2half(h)) << 16);
}
// softplus with ONE MUFU: t=exp(-|x|); log1p(t) via deg-6 poly on v=(2t-1)/3.
__device__ __forceinline__ float softplus_f(float x) {
  float t = __expf(-fabsf(x));
  float v = fmaf(t, 0.6666666667f, -0.3333333333f);
  float p = -0.1666666667f;
  p = fmaf(p, v, 0.2f);
  p = fmaf(p, v, -0.25f);
  p = fmaf(p, v, 0.3333333333f);
  p = fmaf(p, v, -0.5f);
  p = fmaf(p, v, 1.0f);
  float l = fmaf(v, p, 0.4054651081f);
  return fmaxf(x, 0.f) + l;
}

// acc[16][4] (+)= rows [m0..m0+15] of (Atile @ Wtile); K=128, optional K-ext.
template <bool EXT, bool ZERO>
__device__ __forceinline__ void warp_gemm(uint32_t smA, uint32_t smW,
                                          uint32_t smAx, uint32_t smWx,
                                          int m0, int lane, float acc[16][4]) {
  if (ZERO) {
#pragma unroll
    for (int f = 0; f < 16; ++f)
#pragma unroll
      for (int e = 0; e < 4; ++e) acc[f][e] = 0.f;
  }
  const int mid = lane >> 3;
  const int wi  = lane & 7;
  const int arow = m0 + wi + (mid & 1) * 8;
  const uint32_t arow_base = smA + (uint32_t)arow * 256u;
  const int ar7 = arow & 7;

#pragma unroll
  for (int k = 0; k < 8; ++k) {
    const int k0 = k * 16;
    int cha = (k0 >> 3) + (mid >> 1);
    uint32_t a0, a1, a2, a3;
    ldsm4(a0, a1, a2, a3, arow_base + (uint32_t)(((cha ^ ar7) & 15) << 4));
    const int krow = k0 + wi + (mid & 1) * 8;
    const uint32_t brow_base = smW + (uint32_t)krow * 256u;
    const int kr7 = krow & 7;
#pragma unroll
    for (int nf2 = 0; nf2 < 8; ++nf2) {
      int chb = (nf2 << 1) + (mid >> 1);
      uint32_t b0, b1, b2, b3;
      ldsm4t(b0, b1, b2, b3, brow_base + (uint32_t)(((chb ^ kr7) & 15) << 4));
      mma16816(acc[2 * nf2],     a0, a1, a2, a3, b0, b1);
      mma16816(acc[2 * nf2 + 1], a0, a1, a2, a3, b2, b3);
    }
  }
  if (EXT) {
    uint32_t a0, a1, a2, a3;
    ldsm4(a0, a1, a2, a3,
          smAx + (uint32_t)arow * 48u + (uint32_t)((mid >> 1) << 4));
    const int krowe = wi + (mid & 1) * 8;
    const uint32_t brow_base = smWx + (uint32_t)krowe * 256u;
    const int kr7e = krowe & 7;
#pragma unroll
    for (int nf2 = 0; nf2 < 8; ++nf2) {
      int chb = (nf2 << 1) + (mid >> 1);
      uint32_t b0, b1, b2, b3;
      ldsm4t(b0, b1, b2, b3, brow_base + (uint32_t)(((chb ^ kr7e) & 15) << 4));
      mma16816(acc[2 * nf2],     a0, a1, a2, a3, b0, b1);
      mma16816(acc[2 * nf2 + 1], a0, a1, a2, a3, b2, b3);
    }
  }
}

__global__ void zero_kernel() {
  int i = blockIdx.x * 256 + threadIdx.x;
  if (i < NNODES * H) g_mh[i] = 0.f;
  if (i < NNODES * 2) g_mv[i] = 0.f;
  if (i < NNODES)     g_cnt[i] = 0.f;
}

// ------------------------------ edge kernel --------------------------------
__global__ void __launch_bounds__(512, 1) edge_kernel(EdgeParams p) {
  extern __shared__ __align__(1024) char sm[];
  const int tid  = threadIdx.x;
  const int wid  = tid >> 5;
  const int lane = tid & 31;

  // ---------------- prologue ----------------
  {
    const float* Wm[4] = {p.We1, p.Wv1, p.We2, p.We3};
#pragma unroll 1
    for (int m = 0; m < 4; ++m) {
      const float* W = Wm[m];
      char* base = sm + m * 32768;
      for (int i = tid; i < 4096; i += 512) {
        int k  = i >> 5;
        int c4 = (i & 31) << 2;
        float4 w = *(const float4*)(W + k * 128 + c4);
        uint2 pk;
        pk.x = h2pack(w.x, w.y);
        pk.y = h2pack(w.z, w.w);
        *(uint2*)(base + swb(k, c4)) = pk;
      }
    }
    const float* Wx[2] = {p.We1, p.Wv1};
    const int    Ox[2] = {OWX_E1, OWX_V1};
#pragma unroll 1
    for (int m = 0; m < 2; ++m) {
      const float* W = Wx[m];
      char* base = sm + Ox[m];
      for (int i = tid; i < 512; i += 512) {
        int row = i >> 5;
        int c4  = (i & 31) << 2;
        float sc = (row == 4) ? 4.f : 1.f;
        float w0 = 0.f, w1 = 0.f, w2 = 0.f, w3 = 0.f;
        if (row < 5) {
          const float* wr = W + (128 + row) * 128 + c4;
          w0 = wr[0] * sc; w1 = wr[1] * sc; w2 = wr[2] * sc; w3 = wr[3] * sc;
        }
        uint2 pk;
        pk.x = h2pack(w0, w1);
        pk.y = h2pack(w2, w3);
        *(uint2*)(base + swb(row, c4)) = pk;
      }
    }
    if (tid < 128) {
      ((float*)(sm + O_BE1))[tid]  = p.be1[tid];
      ((float*)(sm + O_GE1))[tid]  = p.ge1[tid];
      ((float*)(sm + O_BTE1))[tid] = p.bte1[tid];
      ((float*)(sm + O_BV1))[tid]  = p.bv1[tid];
      ((float*)(sm + O_GV1))[tid]  = p.gv1[tid];
      ((float*)(sm + O_BTV1))[tid] = p.btv1[tid];
      ((float*)(sm + O_WV2))[tid]  = p.Wv2[tid];
      ((float*)(sm + O_BE2))[tid]  = p.be2[tid];
      ((float*)(sm + O_BE3))[tid]  = p.be3[tid];
    }
    if (tid == 0) ((float*)(sm + O_BV2))[0] = p.bv2[0];
  }

  const uint32_t smb  = smem_u32(sm);
  const uint32_t bufA = smb + OACTA;
  const uint32_t bufAx= smb + OACTX;
  const uint32_t wE1  = smb + OW_E1;
  const uint32_t wV1  = smb + OW_V1;
  const uint32_t wE2  = smb + OW_E2;
  const uint32_t wE3  = smb + OW_E3;
  const uint32_t wxE1 = smb + OWX_E1;
  const uint32_t wxV1 = smb + OWX_V1;

  int*   sDst = (int*)(sm + O_DST);
  float* sRel = (float*)(sm + O_REL);
  const float* cBE1 = (const float*)(sm + O_BE1);
  const float* cGE1 = (const float*)(sm + O_GE1);
  const float* cBT1 = (const float*)(sm + O_BTE1);
  const float* cBV1 = (const float*)(sm + O_BV1);
  const float* cGV1 = (const float*)(sm + O_GV1);
  const float* cBTV = (const float*)(sm + O_BTV1);
  const float* cWV2 = (const float*)(sm + O_WV2);
  const float* cBE2 = (const float*)(sm + O_BE2);
  const float* cBE3 = (const float*)(sm + O_BE3);

  const int g  = lane >> 2;
  const int q  = lane & 3;
  const int m0 = wid * 16;
  const int rA = m0 + g;
  const int rB = rA + 8;

  float acc[16][4];

  // prefetch registers (live across the loop-top barrier; acc is dead there)
  float4 vr0[8];
  int    nid1[8];
  int    pf_s = 0, pf_d = 0;
  float2 pf_ps, pf_pd, pf_vs, pf_vd;

  auto prefetch = [&](int t) {
    int e0p = t * ETILE;
    if (tid < ETILE) {
      pf_s  = p.ei[e0p + tid];
      pf_d  = p.ei[NEDGES + e0p + tid];
      pf_ps = ((const float2*)p.pos)[pf_s];
      pf_pd = ((const float2*)p.pos)[pf_d];
      pf_vs = ((const float2*)p.vel)[pf_s];
      pf_vd = ((const float2*)p.vel)[pf_d];
    }
#pragma unroll
    for (int u = 0; u < 8; ++u) {
      int i = tid + u * 512;
      int e = i >> 5, qq = i & 31;
      int half = qq >> 4, c4 = qq & 15;
      int node = p.ei[(half ? 0 : NEDGES) + e0p + e];
      vr0[u] = ((const float4*)p.x)[node * 16 + c4];
    }
#pragma unroll
    for (int u = 0; u < 8; ++u) {
      int i = tid + (8 + u) * 512;
      int e = i >> 5, qq = i & 31;
      int half = qq >> 4;
      nid1[u] = p.ei[(half ? 0 : NEDGES) + e0p + e];
    }
  };

  __syncthreads();  // prologue smem ready
  prefetch(blockIdx.x);

#pragma unroll 1
  for (int tile = blockIdx.x; tile < NTILES; tile += gridDim.x) {
    __syncthreads();  // bufA/bufAx/sDst free

    // ------------- store prefetched geometry -------------
    if (tid < ETILE) {
      sDst[tid] = pf_d;
      float rpx = pf_ps.x - pf_pd.x, rpy = pf_ps.y - pf_pd.y;
      float rvx = pf_vs.x - pf_vd.x, rvy = pf_vs.y - pf_vd.y;
      float dist = rpx * rpx + rpy * rpy;
      float dvr  = rvx * rpx + rvy * rpy;
      float r2   = fminf(1.f / (dist + 0.05f), 20.f);
      float r6   = fminf(r2 * r2 * r2, 400.f);
      float r12  = fminf(r6 * r6, 160000.f);
      uint4 lo;
      lo.x = h2pack(dist, dvr);
      lo.y = h2pack(r2, r6);
      lo.z = h2pack(r12 * 0.25f, 0.f);
      lo.w = 0u;
      *(uint4*)(sm + OACTX + tid * 48)      = lo;
      *(uint4*)(sm + OACTX + tid * 48 + 16) = make_uint4(0u, 0u, 0u, 0u);
      sRel[2 * tid]     = rpx;
      sRel[2 * tid + 1] = rpy;
    }
    // ------------- store batch0 (prefetched), load+store batch1 -------------
#pragma unroll
    for (int u = 0; u < 8; ++u) {
      int i = tid + u * 512;
      int e = i >> 5, qq = i & 31;
      int half = qq >> 4, c4 = qq & 15;
      uint2 pk;
      pk.x = h2pack(vr0[u].x, vr0[u].y);
      pk.y = h2pack(vr0[u].z, vr0[u].w);
      *(uint2*)(sm + OACTA + swb(e, half * 64 + c4 * 4)) = pk;
    }
    {
      float4 vr1[8];
#pragma unroll
      for (int u = 0; u < 8; ++u) {
        int i = tid + (8 + u) * 512;
        int c4 = i & 15;
        vr1[u] = ((const float4*)p.x)[nid1[u] * 16 + c4];
      }
#pragma unroll
      for (int u = 0; u < 8; ++u) {
        int i = tid + (8 + u) * 512;
        int e = i >> 5, qq = i & 31;
        int half = qq >> 4, c4 = qq & 15;
        uint2 pk;
        pk.x = h2pack(vr1[u].x, vr1[u].y);
        pk.y = h2pack(vr1[u].z, vr1[u].w);
        *(uint2*)(sm + OACTA + swb(e, half * 64 + c4 * 4)) = pk;
      }
    }
    __syncthreads();

    // ================= stage 1: V = [A|feat] @ Wv1 (K=144) =================
    warp_gemm<true, true>(bufA, wV1, bufAx, wxV1, m0, lane, acc);
    {
      float sa = 0.f, s2a = 0.f, sb = 0.f, s2b = 0.f;
#pragma unroll
      for (int f = 0; f < 16; ++f) {
#pragma unroll
        for (int t = 0; t < 2; ++t) {
          int c = 8 * f + 2 * q + t;
          float bb = cBV1[c];
          float za = acc[f][t] + bb;
          float zb = acc[f][2 + t] + bb;
          acc[f][t] = za;
          acc[f][2 + t] = zb;
          sa += za; s2a = fmaf(za, za, s2a);
          sb += zb; s2b = fmaf(zb, zb, s2b);
        }
      }
#pragma unroll
      for (int m = 1; m < 4; m <<= 1) {
        sa  += __shfl_xor_sync(0xffffffffu, sa, m);
        s2a += __shfl_xor_sync(0xffffffffu, s2a, m);
        sb  += __shfl_xor_sync(0xffffffffu, sb, m);
        s2b += __shfl_xor_sync(0xffffffffu, s2b, m);
      }
      float mua = sa * (1.f / 128.f);
      float ria = rsqrtf(s2a * (1.f / 128.f) - mua * mua + 1e-5f);
      float mub = sb * (1.f / 128.f);
      float rib = rsqrtf(s2b * (1.f / 128.f) - mub * mub + 1e-5f);
      float va = 0.f, vb = 0.f;
#pragma unroll
      for (int f = 0; f < 16; ++f) {
#pragma unroll
        for (int t = 0; t < 2; ++t) {
          int c = 8 * f + 2 * q + t;
          float gv = cGV1[c], bt = cBTV[c], wv = cWV2[c];
          va += softplus_f((acc[f][t] - mua) * ria * gv + bt) * wv;
          vb += softplus_f((acc[f][2 + t] - mub) * rib * gv + bt) * wv;
        }
      }
#pragma unroll
      for (int m = 1; m < 4; m <<= 1) {
        va += __shfl_xor_sync(0xffffffffu, va, m);
        vb += __shfl_xor_sync(0xffffffffu, vb, m);
      }
      if (q == 0) {
        float bv2v = ((const float*)(sm + O_BV2))[0];
        int dA = sDst[rA];
        float vwa = va + bv2v;
        red2(&g_mv[2 * dA], vwa * sRel[2 * rA], vwa * sRel[2 * rA + 1]);
        atomicAdd(&g_cnt[dA], 1.f);
        int dB = sDst[rB];
        float vwb = vb + bv2v;
        red2(&g_mv[2 * dB], vwb * sRel[2 * rB], vwb * sRel[2 * rB + 1]);
        atomicAdd(&g_cnt[dB], 1.f);
      }
    }

    // ================= stage 2: E1 -> H1 in place =================
    warp_gemm<true, true>(bufA, wE1, bufAx, wxE1, m0, lane, acc);
    {
      float sa = 0.f, s2a = 0.f, sb = 0.f, s2b = 0.f;
#pragma unroll
      for (int f = 0; f < 16; ++f) {
#pragma unroll
        for (int t = 0; t < 2; ++t) {
          int c = 8 * f + 2 * q + t;
          float bb = cBE1[c];
          float za = acc[f][t] + bb;
          float zb = acc[f][2 + t] + bb;
          acc[f][t] = za;
          acc[f][2 + t] = zb;
          sa += za; s2a = fmaf(za, za, s2a);
          sb += zb; s2b = fmaf(zb, zb, s2b);
        }
      }
#pragma unroll
      for (int m = 1; m < 4; m <<= 1) {
        sa  += __shfl_xor_sync(0xffffffffu, sa, m);
        s2a += __shfl_xor_sync(0xffffffffu, s2a, m);
        sb  += __shfl_xor_sync(0xffffffffu, sb, m);
        s2b += __shfl_xor_sync(0xffffffffu, s2b, m);
      }
      float mua = sa * (1.f / 128.f);
      float ria = rsqrtf(s2a * (1.f / 128.f) - mua * mua + 1e-5f);
      float mub = sb * (1.f / 128.f);
      float rib = rsqrtf(s2b * (1.f / 128.f) - mub * mub + 1e-5f);
#pragma unroll
      for (int f = 0; f < 16; ++f) {
        int c0 = 8 * f + 2 * q;
        float ha0 = softplus_f((acc[f][0] - mua) * ria * cGE1[c0] + cBT1[c0]);
        float ha1 = softplus_f((acc[f][1] - mua) * ria * cGE1[c0 + 1] + cBT1[c0 + 1]);
        float hb0 = softplus_f((acc[f][2] - mub) * rib * cGE1[c0] + cBT1[c0]);
        float hb1 = softplus_f((acc[f][3] - mub) * rib * cGE1[c0 + 1] + cBT1[c0 + 1]);
        *(uint32_t*)(sm + OACTA + swb(rA, c0)) = h2pack(ha0, ha1);
        *(uint32_t*)(sm + OACTA + swb(rB, c0)) = h2pack(hb0, hb1);
      }
    }

    // ================= stage 3: E2 -> H2 in place =================
    __syncwarp();
    warp_gemm<false, true>(bufA, wE2, 0, 0, m0, lane, acc);
    {
#pragma unroll
      for (int f = 0; f < 16; ++f) {
        int c0 = 8 * f + 2 * q;
        float b0 = cBE2[c0], b1 = cBE2[c0 + 1];
        float ha0 = softplus_f(acc[f][0] + b0);
        float ha1 = softplus_f(acc[f][1] + b1);
        float hb0 = softplus_f(acc[f][2] + b0);
        float hb1 = softplus_f(acc[f][3] + b1);
        *(uint32_t*)(sm + OACTA + swb(rA, c0)) = h2pack(ha0, ha1);
        *(uint32_t*)(sm + OACTA + swb(rB, c0)) = h2pack(hb0, hb1);
      }
    }

    // ================= stage 4: E3 -> scatter =================
    __syncwarp();
    warp_gemm<false, true>(bufA, wE3, 0, 0, m0, lane, acc);
    {
      int dA = sDst[rA], dB = sDst[rB];
      float* gpa = g_mh + dA * H;
      float* gpb = g_mh + dB * H;
      const bool odd = (q & 1);
#pragma unroll
      for (int f = 0; f < 16; ++f) {
        int c0 = 8 * f + 2 * q;
        float b0 = cBE3[c0], b1 = cBE3[c0 + 1];
        float a0 = acc[f][0] + b0;
        float a1 = acc[f][1] + b1;
        float a2 = acc[f][2] + b0;
        float a3 = acc[f][3] + b1;
        float u0 = __shfl_xor_sync(0xffffffffu, odd ? a0 : a2, 1);
        float u1 = __shfl_xor_sync(0xffffffffu, odd ? a1 : a3, 1);
        float* ptr = odd ? (gpb + c0 - 2) : (gpa + c0);
        float v0 = odd ? u0 : a0;
        float v1 = odd ? u1 : a1;
        float v2 = odd ? a2 : u0;
        float v3 = odd ? a3 : u1;
        red4(ptr, v0, v1, v2, v3);
      }
    }

    // ------------- prefetch next tile (hides LDG latency behind barrier) ---
    int nt = tile + gridDim.x;
    if (nt < NTILES) prefetch(nt);
  }
}

// ------------------------------ node kernel (HMMA) --------------------------
__global__ void __launch_bounds__(512, 1) node_kernel(NodeParams p) {
  extern __shared__ __align__(1024) char sm[];
  const int tid  = threadIdx.x;
  const int wid  = tid >> 5;
  const int lane = tid & 31;
  const int n0   = blockIdx.x * 256;

  {
    for (int i = tid; i < 4096; i += 512) {
      int k  = i >> 5;
      int c4 = (i & 31) << 2;
      float4 w = *(const float4*)(p.Wh1 + k * 128 + c4);
      uint2 pk;
      pk.x = h2pack(w.x, w.y);
      pk.y = h2pack(w.z, w.w);
      *(uint2*)(sm + ON_W1a + swb(k, c4)) = pk;
    }
    for (int i = tid; i < 4096; i += 512) {
      int k  = i >> 5;
      int c4 = (i & 31) << 2;
      float4 w = make_float4(0.f, 0.f, 0.f, 0.f);
      if (k < 65) w = *(const float4*)(p.Wh1 + (128 + k) * 128 + c4);
      uint2 pk;
      pk.x = h2pack(w.x, w.y);
      pk.y = h2pack(w.z, w.w);
      *(uint2*)(sm + ON_W1b + swb(k, c4)) = pk;
    }
    for (int i = tid; i < 4096; i += 512) {
      int k  = i >> 5;
      int c4 = (i & 31) << 2;
      float4 w = make_float4(0.f, 0.f, 0.f, 0.f);
      if (c4 < 64) w = *(const float4*)(p.Wh2 + k * 64 + c4);
      uint2 pk;
      pk.x = h2pack(w.x, w.y);
      pk.y = h2pack(w.z, w.w);
      *(uint2*)(sm + ON_W2 + swb(k, c4)) = pk;
    }
    if (tid < 128) {
      ((float*)(sm + ON_BH1))[tid]  = p.bh1[tid];
      ((float*)(sm + ON_GH1))[tid]  = p.gh1[tid];
      ((float*)(sm + ON_BTH1))[tid] = p.bth1[tid];
    }
    if (tid < 64) ((float*)(sm + ON_BH2))[tid] = p.bh2[tid];
  }

  float* sRden = (float*)(sm + ON_RDEN);

  if (tid < 256) {
    int n = n0 + tid;
    float den = 1.f, nrm = 0.f;
    if (n < NNODES) {
      den = fmaxf(g_cnt[n], 1.f);
      float mvx = g_mv[2 * n] / den + 1e-8f;
      float mvy = g_mv[2 * n + 1] / den + 1e-8f;
      nrm = sqrtf(mvx * mvx + mvy * mvy);
    }
    sRden[tid] = 1.f / den;
    *(uint2*)(sm + ON_A2 + swb(tid, 64)) = make_uint2(h2pack(nrm, 0.f), 0u);
    uint2 z = make_uint2(0u, 0u);
#pragma unroll
    for (int gg = 1; gg < 16; ++gg)
      *(uint2*)(sm + ON_A2 + swb(tid, 64 + gg * 4)) = z;
  }
  __syncthreads();

  for (int i = tid; i < 256 * 32; i += 512) {
    int row = i >> 5, grp = i & 31;
    int n = n0 + row;
    float4 w = make_float4(0.f, 0.f, 0.f, 0.f);
    if (n < NNODES) {
      if (grp < 16) {
        w = *(const float4*)(p.x + n * 64 + grp * 4);
      } else {
        w = *(const float4*)(g_mh + n * 128 + (grp - 16) * 4);
        float rd = sRden[row];
        w.x *= rd; w.y *= rd; w.z *= rd; w.w *= rd;
      }
    }
    uint2 pk;
    pk.x = h2pack(w.x, w.y);
    pk.y = h2pack(w.z, w.w);
    *(uint2*)(sm + ON_A1 + swb(row, grp * 4)) = pk;
  }
  for (int i = tid; i < 256 * 16; i += 512) {
    int row = i >> 4, grp = i & 15;
    int n = n0 + row;
    float4 w = make_float4(0.f, 0.f, 0.f, 0.f);
    if (n < NNODES) {
      w = *(const float4*)(g_mh + n * 128 + 64 + grp * 4);
      float rd = sRden[row];
      w.x *= rd; w.y *= rd; w.z *= rd; w.w *= rd;
    }
    uint2 pk;
    pk.x = h2pack(w.x, w.y);
    pk.y = h2pack(w.z, w.w);
    *(uint2*)(sm + ON_A2 + swb(row, grp * 4)) = pk;
  }
  __syncthreads();

  const uint32_t smb = smem_u32(sm);
  const int g  = lane >> 2;
  const int q  = lane & 3;
  const int m0 = wid * 16;
  const int rA = m0 + g;
  const int rB = rA + 8;
  const float* cBH1 = (const float*)(sm + ON_BH1);
  const float* cGH1 = (const float*)(sm + ON_GH1);
  const float* cBT1 = (const float*)(sm + ON_BTH1);
  const float* cBH2 = (const float*)(sm + ON_BH2);

  float acc[16][4];
  warp_gemm<false, true>(smb + ON_A1, smb + ON_W1a, 0, 0, m0, lane, acc);
  warp_gemm<false, false>(smb + ON_A2, smb + ON_W1b, 0, 0, m0, lane, acc);
  {
    float sa = 0.f, s2a = 0.f, sb = 0.f, s2b = 0.f;
#pragma unroll
    for (int f = 0; f < 16; ++f) {
#pragma unroll
      for (int t = 0; t < 2; ++t) {
        int c = 8 * f + 2 * q + t;
        float bb = cBH1[c];
        float za = acc[f][t] + bb;
        float zb = acc[f][2 + t] + bb;
        acc[f][t] = za;
        acc[f][2 + t] = zb;
        sa += za; s2a = fmaf(za, za, s2a);
        sb += zb; s2b = fmaf(zb, zb, s2b);
      }
    }
#pragma unroll
    for (int m = 1; m < 4; m <<= 1) {
      sa  += __shfl_xor_sync(0xffffffffu, sa, m);
      s2a += __shfl_xor_sync(0xffffffffu, s2a, m);
      sb  += __shfl_xor_sync(0xffffffffu, sb, m);
      s2b += __shfl_xor_sync(0xffffffffu, s2b, m);
    }
    float mua = sa * (1.f / 128.f);
    float ria = rsqrtf(s2a * (1.f / 128.f) - mua * mua + 1e-5f);
    float mub = sb * (1.f / 128.f);
    float rib = rsqrtf(s2b * (1.f / 128.f) - mub * mub + 1e-5f);
#pragma unroll
    for (int f = 0; f < 16; ++f) {
      int c0 = 8 * f + 2 * q;
      float ha0 = softplus_f((acc[f][0] - mua) * ria * cGH1[c0] + cBT1[c0]);
      float ha1 = softplus_f((acc[f][1] - mua) * ria * cGH1[c0 + 1] + cBT1[c0 + 1]);
      float hb0 = softplus_f((acc[f][2] - mub) * rib * cGH1[c0] + cBT1[c0]);
      float hb1 = softplus_f((acc[f][3] - mub) * rib * cGH1[c0 + 1] + cBT1[c0 + 1]);
      *(uint32_t*)(sm + ON_A1 + swb(rA, c0)) = h2pack(ha0, ha1);
      *(uint32_t*)(sm + ON_A1 + swb(rB, c0)) = h2pack(hb0, hb1);
    }
  }
  __syncwarp();
  warp_gemm<false, true>(smb + ON_A1, smb + ON_W2, 0, 0, m0, lane, acc);
  {
    int nA = n0 + rA, nB = n0 + rB;
#pragma unroll
    for (int f = 0; f < 8; ++f) {
      int c0 = 8 * f + 2 * q;
      float b0 = cBH2[c0], b1 = cBH2[c0 + 1];
      if (nA < NNODES) {
        float2 xv = *(const float2*)(p.x + nA * 64 + c0);
        float2 o;
        o.x = xv.x + acc[f][0] + b0;
        o.y = xv.y + acc[f][1] + b1;
        *(float2*)(p.out + nA * 64 + c0) = o;
      }
      if (nB < NNODES) {
        float2 xv = *(const float2*)(p.x + nB * 64 + c0);
        float2 o;
        o.x = xv.x + acc[f][2] + b0;
        o.y = xv.y + acc[f][3] + b1;
        *(float2*)(p.out + nB * 64 + c0) = o;
      }
    }
  }
}

// ------------------------------ launch -------------------------------------
extern "C" void kernel_launch(void* const* d_in, const int* in_sizes, int n_in,
                              void* d_out, int out_size) {
  EdgeParams ep;
  ep.x    = (const float*)d_in[0];
  ep.pos  = (const float*)d_in[1];
  ep.vel  = (const float*)d_in[2];
  ep.We1  = (const float*)d_in[3];
  ep.be1  = (const float*)d_in[4];
  ep.ge1  = (const float*)d_in[5];
  ep.bte1 = (const float*)d_in[6];
  ep.We2  = (const float*)d_in[7];
  ep.be2  = (const float*)d_in[8];
  ep.We3  = (const float*)d_in[9];
  ep.be3  = (const float*)d_in[10];
  ep.Wv1  = (const float*)d_in[11];
  ep.bv1  = (const float*)d_in[12];
  ep.gv1  = (const float*)d_in[13];
  ep.btv1 = (const float*)d_in[14];
  ep.Wv2  = (const float*)d_in[15];
  ep.bv2  = (const float*)d_in[16];
  ep.ei   = (const int*)d_in[23];

  NodeParams np;
  np.x    = ep.x;
  np.Wh1  = (const float*)d_in[17];
  np.bh1  = (const float*)d_in[18];
  np.gh1  = (const float*)d_in[19];
  np.bth1 = (const float*)d_in[20];
  np.Wh2  = (const float*)d_in[21];
  np.bh2  = (const float*)d_in[22];
  np.out  = (float*)d_out;

  cudaFuncSetAttribute(edge_kernel, cudaFuncAttributeMaxDynamicSharedMemorySize,
                       EDGE_SMEM);
  cudaFuncSetAttribute(node_kernel, cudaFuncAttributeMaxDynamicSharedMemorySize,
                       NODE_SMEM);

  zero_kernel<<<(NNODES * H + 255) / 256, 256>>>();
  edge_kernel<<<148, 512, EDGE_SMEM>>>(ep);
  node_kernel<<<NODE_CTAS, 512, NODE_SMEM>>>(np);
}

// round 17
// speedup vs baseline: 1.1240x; 1.1240x over previous
#include <cuda_runtime.h>
#include <cuda_fp16.h>
#include <cstdint>

// ---------------------------------------------------------------------------
// R11: barrier-free edge kernel. Each warp owns an independent stream of
//      16-edge chunks (grid-stride over 40000 chunks): loads its own indices
//      (1 ei load/lane + shfl), computes geometry (lanes 0..15), gathers its
//      own 16 A-rows, then V/E1/E2/E3 + scatter — all warp-local, only
//      __syncwarp. No block barriers in the loop, no prefetch machinery.
//      Stage arithmetic identical to R8 (492us): __logf softplus, H1/H2 via
//      smem in-place, red.v4/v2 scatter, K=144 feature folding.
// Node kernel: HMMA (unchanged from R8).
// ---------------------------------------------------------------------------

namespace {
constexpr int NNODES = 20000;
constexpr int NEDGES = 640000;
constexpr int H      = 128;
constexpr int NCHUNKS = NEDGES / 16;     // 40000 warp-chunks

// ---- edge smem layout ----
constexpr int OW_E1  = 0;
constexpr int OW_V1  = 32768;
constexpr int OW_E2  = 65536;
constexpr int OW_E3  = 98304;
constexpr int OWX_E1 = 131072;
constexpr int OWX_V1 = 135168;
constexpr int OACTA  = 139264;   // 256 rows x 256 B (16 rows per warp)
constexpr int OACTX  = 204800;   // 256 rows x 48 B
constexpr int O_BE1  = 217088;
constexpr int O_GE1  = 217600;
constexpr int O_BTE1 = 218112;
constexpr int O_BV1  = 218624;
constexpr int O_GV1  = 219136;
constexpr int O_BTV1 = 219648;
constexpr int O_WV2  = 220160;
constexpr int O_BE2  = 220672;
constexpr int O_BE3  = 221184;
constexpr int O_REL  = 221696;
constexpr int O_DST  = 223744;
constexpr int O_BV2  = 224768;
constexpr int EDGE_SMEM = 224896;

// ---- node smem layout ----
constexpr int ON_A1   = 0;
constexpr int ON_A2   = 65536;
constexpr int ON_W1a  = 131072;
constexpr int ON_W1b  = 163840;
constexpr int ON_W2   = 196608;
constexpr int ON_BH1  = 229376;
constexpr int ON_GH1  = 229888;
constexpr int ON_BTH1 = 230400;
constexpr int ON_BH2  = 230912;
constexpr int ON_RDEN = 231168;
constexpr int NODE_SMEM = 232192;
constexpr int NODE_CTAS = (NNODES + 255) / 256;  // 79
}  // namespace

__device__ __align__(16) float g_mh[NNODES * H];
__device__ __align__(16) float g_mv[NNODES * 2];
__device__ float g_cnt[NNODES];

struct EdgeParams {
  const float *x, *pos, *vel;
  const float *We1, *be1, *ge1, *bte1, *We2, *be2, *We3, *be3;
  const float *Wv1, *bv1, *gv1, *btv1, *Wv2, *bv2;
  const int   *ei;
};
struct NodeParams {
  const float *x;
  const float *Wh1, *bh1, *gh1, *bth1, *Wh2, *bh2;
  float       *out;
};

// ------------------------------- helpers -----------------------------------
__device__ __forceinline__ uint32_t smem_u32(const void* p) {
  uint32_t a;
  asm("{ .reg .u64 t; cvta.to.shared.u64 t, %1; cvt.u32.u64 %0, t; }"
      : "=r"(a) : "l"(p));
  return a;
}
__device__ __forceinline__ void ldsm4(uint32_t& a0, uint32_t& a1, uint32_t& a2,
                                      uint32_t& a3, uint32_t addr) {
  asm volatile(
      "ldmatrix.sync.aligned.m8n8.x4.shared.b16 {%0,%1,%2,%3}, [%4];"
      : "=r"(a0), "=r"(a1), "=r"(a2), "=r"(a3) : "r"(addr));
}
__device__ __forceinline__ void ldsm4t(uint32_t& a0, uint32_t& a1, uint32_t& a2,
                                       uint32_t& a3, uint32_t addr) {
  asm volatile(
      "ldmatrix.sync.aligned.m8n8.x4.trans.shared.b16 {%0,%1,%2,%3}, [%4];"
      : "=r"(a0), "=r"(a1), "=r"(a2), "=r"(a3) : "r"(addr));
}
__device__ __forceinline__ void mma16816(float* c, uint32_t a0, uint32_t a1,
                                         uint32_t a2, uint32_t a3, uint32_t b0,
                                         uint32_t b1) {
  asm volatile(
      "mma.sync.aligned.m16n8k16.row.col.f32.f16.f16.f32 "
      "{%0,%1,%2,%3}, {%4,%5,%6,%7}, {%8,%9}, {%0,%1,%2,%3};"
      : "+f"(c[0]), "+f"(c[1]), "+f"(c[2]), "+f"(c[3])
      : "r"(a0), "r"(a1), "r"(a2), "r"(a3), "r"(b0), "r"(b1));
}
__device__ __forceinline__ void red4(float* p, float a, float b, float c,
                                     float d) {
  asm volatile("red.global.add.v4.f32 [%0], {%1,%2,%3,%4};"
               :: "l"(p), "f"(a), "f"(b), "f"(c), "f"(d) : "memory");
}
__device__ __forceinline__ void red2(float* p, float a, float b) {
  asm volatile("red.global.add.v2.f32 [%0], {%1,%2};"
               :: "l"(p), "f"(a), "f"(b) : "memory");
}
__device__ __forceinline__ uint32_t swb(int row, int col) {
  return (uint32_t)row * 256u + (uint32_t)((((col >> 3) ^ (row & 7)) & 15) << 4) +
         (uint32_t)((col & 7) << 1);
}
__device__ __forceinline__ uint32_t h2pack(float a, float b) {
  __half2 h = __floats2half2_rn(a, b);
  return (uint32_t)__half_as_ushort(__low2half(h)) |
         ((uint32_t)__half_as_ushort(__high2half(h)) << 16);
}
// 2-MUFU softplus (R8 form — the poly variant regressed: issue-bound kernel).
__device__ __forceinline__ float softplus_f(float v) {
  return fmaxf(v, 0.f) + __logf(1.f + __expf(-fabsf(v)));
}

// acc[16][4] (+)= rows [m0..m0+15] of (Atile @ Wtile); K=128, optional K-ext.
template <bool EXT, bool ZERO>
__device__ __forceinline__ void warp_gemm(uint32_t smA, uint32_t smW,
                                          uint32_t smAx, uint32_t smWx,
                                          int m0, int lane, float acc[16][4]) {
  if (ZERO) {
#pragma unroll
    for (int f = 0; f < 16; ++f)
#pragma unroll
      for (int e = 0; e < 4; ++e) acc[f][e] = 0.f;
  }
  const int mid = lane >> 3;
  const int wi  = lane & 7;
  const int arow = m0 + wi + (mid & 1) * 8;
  const uint32_t arow_base = smA + (uint32_t)arow * 256u;
  const int ar7 = arow & 7;

#pragma unroll
  for (int k = 0; k < 8; ++k) {
    const int k0 = k * 16;
    int cha = (k0 >> 3) + (mid >> 1);
    uint32_t a0, a1, a2, a3;
    ldsm4(a0, a1, a2, a3, arow_base + (uint32_t)(((cha ^ ar7) & 15) << 4));
    const int krow = k0 + wi + (mid & 1) * 8;
    const uint32_t brow_base = smW + (uint32_t)krow * 256u;
    const int kr7 = krow & 7;
#pragma unroll
    for (int nf2 = 0; nf2 < 8; ++nf2) {
      int chb = (nf2 << 1) + (mid >> 1);
      uint32_t b0, b1, b2, b3;
      ldsm4t(b0, b1, b2, b3, brow_base + (uint32_t)(((chb ^ kr7) & 15) << 4));
      mma16816(acc[2 * nf2],     a0, a1, a2, a3, b0, b1);
      mma16816(acc[2 * nf2 + 1], a0, a1, a2, a3, b2, b3);
    }
  }
  if (EXT) {
    uint32_t a0, a1, a2, a3;
    ldsm4(a0, a1, a2, a3,
          smAx + (uint32_t)arow * 48u + (uint32_t)((mid >> 1) << 4));
    const int krowe = wi + (mid & 1) * 8;
    const uint32_t brow_base = smWx + (uint32_t)krowe * 256u;
    const int kr7e = krowe & 7;
#pragma unroll
    for (int nf2 = 0; nf2 < 8; ++nf2) {
      int chb = (nf2 << 1) + (mid >> 1);
      uint32_t b0, b1, b2, b3;
      ldsm4t(b0, b1, b2, b3, brow_base + (uint32_t)(((chb ^ kr7e) & 15) << 4));
      mma16816(acc[2 * nf2],     a0, a1, a2, a3, b0, b1);
      mma16816(acc[2 * nf2 + 1], a0, a1, a2, a3, b2, b3);
    }
  }
}

__global__ void zero_kernel() {
  int i = blockIdx.x * 256 + threadIdx.x;
  if (i < NNODES * H) g_mh[i] = 0.f;
  if (i < NNODES * 2) g_mv[i] = 0.f;
  if (i < NNODES)     g_cnt[i] = 0.f;
}

// ------------------------------ edge kernel --------------------------------
__global__ void __launch_bounds__(512, 1) edge_kernel(EdgeParams p) {
  extern __shared__ __align__(1024) char sm[];
  const int tid  = threadIdx.x;
  const int wid  = tid >> 5;
  const int lane = tid & 31;

  // ---------------- prologue: weights / params into smem -----------------
  {
    const float* Wm[4] = {p.We1, p.Wv1, p.We2, p.We3};
#pragma unroll 1
    for (int m = 0; m < 4; ++m) {
      const float* W = Wm[m];
      char* base = sm + m * 32768;
      for (int i = tid; i < 4096; i += 512) {
        int k  = i >> 5;
        int c4 = (i & 31) << 2;
        float4 w = *(const float4*)(W + k * 128 + c4);
        uint2 pk;
        pk.x = h2pack(w.x, w.y);
        pk.y = h2pack(w.z, w.w);
        *(uint2*)(base + swb(k, c4)) = pk;
      }
    }
    const float* Wx[2] = {p.We1, p.Wv1};
    const int    Ox[2] = {OWX_E1, OWX_V1};
#pragma unroll 1
    for (int m = 0; m < 2; ++m) {
      const float* W = Wx[m];
      char* base = sm + Ox[m];
      for (int i = tid; i < 512; i += 512) {
        int row = i >> 5;
        int c4  = (i & 31) << 2;
        float sc = (row == 4) ? 4.f : 1.f;
        float w0 = 0.f, w1 = 0.f, w2 = 0.f, w3 = 0.f;
        if (row < 5) {
          const float* wr = W + (128 + row) * 128 + c4;
          w0 = wr[0] * sc; w1 = wr[1] * sc; w2 = wr[2] * sc; w3 = wr[3] * sc;
        }
        uint2 pk;
        pk.x = h2pack(w0, w1);
        pk.y = h2pack(w2, w3);
        *(uint2*)(base + swb(row, c4)) = pk;
      }
    }
    if (tid < 128) {
      ((float*)(sm + O_BE1))[tid]  = p.be1[tid];
      ((float*)(sm + O_GE1))[tid]  = p.ge1[tid];
      ((float*)(sm + O_BTE1))[tid] = p.bte1[tid];
      ((float*)(sm + O_BV1))[tid]  = p.bv1[tid];
      ((float*)(sm + O_GV1))[tid]  = p.gv1[tid];
      ((float*)(sm + O_BTV1))[tid] = p.btv1[tid];
      ((float*)(sm + O_WV2))[tid]  = p.Wv2[tid];
      ((float*)(sm + O_BE2))[tid]  = p.be2[tid];
      ((float*)(sm + O_BE3))[tid]  = p.be3[tid];
    }
    if (tid == 0) ((float*)(sm + O_BV2))[0] = p.bv2[0];
  }
  __syncthreads();  // weights ready; after this, warps never block-sync again

  const uint32_t smb  = smem_u32(sm);
  const uint32_t bufA = smb + OACTA;
  const uint32_t bufAx= smb + OACTX;
  const uint32_t wE1  = smb + OW_E1;
  const uint32_t wV1  = smb + OW_V1;
  const uint32_t wE2  = smb + OW_E2;
  const uint32_t wE3  = smb + OW_E3;
  const uint32_t wxE1 = smb + OWX_E1;
  const uint32_t wxV1 = smb + OWX_V1;

  int*   sDst = (int*)(sm + O_DST);
  float* sRel = (float*)(sm + O_REL);
  const float* cBE1 = (const float*)(sm + O_BE1);
  const float* cGE1 = (const float*)(sm + O_GE1);
  const float* cBT1 = (const float*)(sm + O_BTE1);
  const float* cBV1 = (const float*)(sm + O_BV1);
  const float* cGV1 = (const float*)(sm + O_GV1);
  const float* cBTV = (const float*)(sm + O_BTV1);
  const float* cWV2 = (const float*)(sm + O_WV2);
  const float* cBE2 = (const float*)(sm + O_BE2);
  const float* cBE3 = (const float*)(sm + O_BE3);
  const float  bv2v = ((const float*)(sm + O_BV2))[0];

  const int g  = lane >> 2;
  const int q  = lane & 3;
  const int m0 = wid * 16;
  const int rA = m0 + g;
  const int rB = rA + 8;
  const int el = lane & 15;        // edge-within-chunk for index/geometry

  const int gwarp  = blockIdx.x * 16 + wid;   // global warp id
  const int nwarps = gridDim.x * 16;          // 2368

  float acc[16][4];

#pragma unroll 1
  for (int chunk = gwarp; chunk < NCHUNKS; chunk += nwarps) {
    const int e0 = chunk * 16;

    // ---- indices: lanes 0..15 load dst, 16..31 load src of edge (lane&15)
    int myidx = p.ei[(lane < 16 ? NEDGES : 0) + e0 + el];
    int sidx  = __shfl_sync(0xffffffffu, myidx, el + 16);  // src of edge el
    // ---- geometry (lanes 0..15, one edge each)
    if (lane < 16) {
      int d = myidx;
      float2 ps = ((const float2*)p.pos)[sidx], pd = ((const float2*)p.pos)[d];
      float2 vs = ((const float2*)p.vel)[sidx], vd = ((const float2*)p.vel)[d];
      float rpx = ps.x - pd.x, rpy = ps.y - pd.y;
      float rvx = vs.x - vd.x, rvy = vs.y - vd.y;
      float dist = rpx * rpx + rpy * rpy;
      float dvr  = rvx * rpx + rvy * rpy;
      float r2   = fminf(1.f / (dist + 0.05f), 20.f);
      float r6   = fminf(r2 * r2 * r2, 400.f);
      float r12  = fminf(r6 * r6, 160000.f);
      int row = m0 + el;
      uint4 lo;
      lo.x = h2pack(dist, dvr);
      lo.y = h2pack(r2, r6);
      lo.z = h2pack(r12 * 0.25f, 0.f);
      lo.w = 0u;
      *(uint4*)(sm + OACTX + row * 48)      = lo;
      *(uint4*)(sm + OACTX + row * 48 + 16) = make_uint4(0u, 0u, 0u, 0u);
      sRel[2 * row]     = rpx;
      sRel[2 * row + 1] = rpy;
      sDst[row] = d;
    }

    // ---- gather own 16 rows: 512 float4 per warp, 16/lane, 2 batches of 8
    const int half = lane >> 4;          // 0: dst cols 0..63, 1: src cols
    const int c4   = lane & 15;
    const int shsrc = lane & 16;         // 0 -> dst lanes, 16 -> src lanes
#pragma unroll 1
    for (int b = 0; b < 2; ++b) {
      float4 vr[8];
#pragma unroll
      for (int u8 = 0; u8 < 8; ++u8) {
        int u = b * 8 + u8;              // row within chunk
        int node = __shfl_sync(0xffffffffu, myidx, shsrc + u);
        vr[u8] = ((const float4*)p.x)[node * 16 + c4];
      }
#pragma unroll
      for (int u8 = 0; u8 < 8; ++u8) {
        int u = b * 8 + u8;
        uint2 pk;
        pk.x = h2pack(vr[u8].x, vr[u8].y);
        pk.y = h2pack(vr[u8].z, vr[u8].w);
        *(uint2*)(sm + OACTA + swb(m0 + u, half * 64 + c4 * 4)) = pk;
      }
    }
    __syncwarp();

    // ================= stage 1: V = [A|feat] @ Wv1 (K=144) =================
    warp_gemm<true, true>(bufA, wV1, bufAx, wxV1, m0, lane, acc);
    {
      float sa = 0.f, s2a = 0.f, sb = 0.f, s2b = 0.f;
#pragma unroll
      for (int f = 0; f < 16; ++f) {
#pragma unroll
        for (int t = 0; t < 2; ++t) {
          int c = 8 * f + 2 * q + t;
          float bb = cBV1[c];
          float za = acc[f][t] + bb;
          float zb = acc[f][2 + t] + bb;
          acc[f][t] = za;
          acc[f][2 + t] = zb;
          sa += za; s2a = fmaf(za, za, s2a);
          sb += zb; s2b = fmaf(zb, zb, s2b);
        }
      }
#pragma unroll
      for (int m = 1; m < 4; m <<= 1) {
        sa  += __shfl_xor_sync(0xffffffffu, sa, m);
        s2a += __shfl_xor_sync(0xffffffffu, s2a, m);
        sb  += __shfl_xor_sync(0xffffffffu, sb, m);
        s2b += __shfl_xor_sync(0xffffffffu, s2b, m);
      }
      float mua = sa * (1.f / 128.f);
      float ria = rsqrtf(s2a * (1.f / 128.f) - mua * mua + 1e-5f);
      float mub = sb * (1.f / 128.f);
      float rib = rsqrtf(s2b * (1.f / 128.f) - mub * mub + 1e-5f);
      float va = 0.f, vb = 0.f;
#pragma unroll
      for (int f = 0; f < 16; ++f) {
#pragma unroll
        for (int t = 0; t < 2; ++t) {
          int c = 8 * f + 2 * q + t;
          float gv = cGV1[c], bt = cBTV[c], wv = cWV2[c];
          va += softplus_f((acc[f][t] - mua) * ria * gv + bt) * wv;
          vb += softplus_f((acc[f][2 + t] - mub) * rib * gv + bt) * wv;
        }
      }
#pragma unroll
      for (int m = 1; m < 4; m <<= 1) {
        va += __shfl_xor_sync(0xffffffffu, va, m);
        vb += __shfl_xor_sync(0xffffffffu, vb, m);
      }
      if (q == 0) {
        int dA = sDst[rA];
        float vwa = va + bv2v;
        red2(&g_mv[2 * dA], vwa * sRel[2 * rA], vwa * sRel[2 * rA + 1]);
        atomicAdd(&g_cnt[dA], 1.f);
        int dB = sDst[rB];
        float vwb = vb + bv2v;
        red2(&g_mv[2 * dB], vwb * sRel[2 * rB], vwb * sRel[2 * rB + 1]);
        atomicAdd(&g_cnt[dB], 1.f);
      }
    }

    // ================= stage 2: E1 -> H1 in place =================
    warp_gemm<true, true>(bufA, wE1, bufAx, wxE1, m0, lane, acc);
    {
      float sa = 0.f, s2a = 0.f, sb = 0.f, s2b = 0.f;
#pragma unroll
      for (int f = 0; f < 16; ++f) {
#pragma unroll
        for (int t = 0; t < 2; ++t) {
          int c = 8 * f + 2 * q + t;
          float bb = cBE1[c];
          float za = acc[f][t] + bb;
          float zb = acc[f][2 + t] + bb;
          acc[f][t] = za;
          acc[f][2 + t] = zb;
          sa += za; s2a = fmaf(za, za, s2a);
          sb += zb; s2b = fmaf(zb, zb, s2b);
        }
      }
#pragma unroll
      for (int m = 1; m < 4; m <<= 1) {
        sa  += __shfl_xor_sync(0xffffffffu, sa, m);
        s2a += __shfl_xor_sync(0xffffffffu, s2a, m);
        sb  += __shfl_xor_sync(0xffffffffu, sb, m);
        s2b += __shfl_xor_sync(0xffffffffu, s2b, m);
      }
      float mua = sa * (1.f / 128.f);
      float ria = rsqrtf(s2a * (1.f / 128.f) - mua * mua + 1e-5f);
      float mub = sb * (1.f / 128.f);
      float rib = rsqrtf(s2b * (1.f / 128.f) - mub * mub + 1e-5f);
#pragma unroll
      for (int f = 0; f < 16; ++f) {
        int c0 = 8 * f + 2 * q;
        float ha0 = softplus_f((acc[f][0] - mua) * ria * cGE1[c0] + cBT1[c0]);
        float ha1 = softplus_f((acc[f][1] - mua) * ria * cGE1[c0 + 1] + cBT1[c0 + 1]);
        float hb0 = softplus_f((acc[f][2] - mub) * rib * cGE1[c0] + cBT1[c0]);
        float hb1 = softplus_f((acc[f][3] - mub) * rib * cGE1[c0 + 1] + cBT1[c0 + 1]);
        *(uint32_t*)(sm + OACTA + swb(rA, c0)) = h2pack(ha0, ha1);
        *(uint32_t*)(sm + OACTA + swb(rB, c0)) = h2pack(hb0, hb1);
      }
    }

    // ================= stage 3: E2 -> H2 in place =================
    __syncwarp();
    warp_gemm<false, true>(bufA, wE2, 0, 0, m0, lane, acc);
    {
#pragma unroll
      for (int f = 0; f < 16; ++f) {
        int c0 = 8 * f + 2 * q;
        float b0 = cBE2[c0], b1 = cBE2[c0 + 1];
        float ha0 = softplus_f(acc[f][0] + b0);
        float ha1 = softplus_f(acc[f][1] + b1);
        float hb0 = softplus_f(acc[f][2] + b0);
        float hb1 = softplus_f(acc[f][3] + b1);
        *(uint32_t*)(sm + OACTA + swb(rA, c0)) = h2pack(ha0, ha1);
        *(uint32_t*)(sm + OACTA + swb(rB, c0)) = h2pack(hb0, hb1);
      }
    }

    // ================= stage 4: E3 -> scatter =================
    __syncwarp();
    warp_gemm<false, true>(bufA, wE3, 0, 0, m0, lane, acc);
    {
      int dA = sDst[rA], dB = sDst[rB];
      float* gpa = g_mh + dA * H;
      float* gpb = g_mh + dB * H;
      const bool odd = (q & 1);
#pragma unroll
      for (int f = 0; f < 16; ++f) {
        int c0 = 8 * f + 2 * q;
        float b0 = cBE3[c0], b1 = cBE3[c0 + 1];
        float a0 = acc[f][0] + b0;
        float a1 = acc[f][1] + b1;
        float a2 = acc[f][2] + b0;
        float a3 = acc[f][3] + b1;
        float u0 = __shfl_xor_sync(0xffffffffu, odd ? a0 : a2, 1);
        float u1 = __shfl_xor_sync(0xffffffffu, odd ? a1 : a3, 1);
        float* ptr = odd ? (gpb + c0 - 2) : (gpa + c0);
        float v0 = odd ? u0 : a0;
        float v1 = odd ? u1 : a1;
        float v2 = odd ? a2 : u0;
        float v3 = odd ? a3 : u1;
        red4(ptr, v0, v1, v2, v3);
      }
    }
    __syncwarp();  // scatter reads of bufA done before next chunk overwrites
  }
}

// ------------------------------ node kernel (HMMA) --------------------------
__global__ void __launch_bounds__(512, 1) node_kernel(NodeParams p) {
  extern __shared__ __align__(1024) char sm[];
  const int tid  = threadIdx.x;
  const int wid  = tid >> 5;
  const int lane = tid & 31;
  const int n0   = blockIdx.x * 256;

  {
    for (int i = tid; i < 4096; i += 512) {
      int k  = i >> 5;
      int c4 = (i & 31) << 2;
      float4 w = *(const float4*)(p.Wh1 + k * 128 + c4);
      uint2 pk;
      pk.x = h2pack(w.x, w.y);
      pk.y = h2pack(w.z, w.w);
      *(uint2*)(sm + ON_W1a + swb(k, c4)) = pk;
    }
    for (int i = tid; i < 4096; i += 512) {
      int k  = i >> 5;
      int c4 = (i & 31) << 2;
      float4 w = make_float4(0.f, 0.f, 0.f, 0.f);
      if (k < 65) w = *(const float4*)(p.Wh1 + (128 + k) * 128 + c4);
      uint2 pk;
      pk.x = h2pack(w.x, w.y);
      pk.y = h2pack(w.z, w.w);
      *(uint2*)(sm + ON_W1b + swb(k, c4)) = pk;
    }
    for (int i = tid; i < 4096; i += 512) {
      int k  = i >> 5;
      int c4 = (i & 31) << 2;
      float4 w = make_float4(0.f, 0.f, 0.f, 0.f);
      if (c4 < 64) w = *(const float4*)(p.Wh2 + k * 64 + c4);
      uint2 pk;
      pk.x = h2pack(w.x, w.y);
      pk.y = h2pack(w.z, w.w);
      *(uint2*)(sm + ON_W2 + swb(k, c4)) = pk;
    }
    if (tid < 128) {
      ((float*)(sm + ON_BH1))[tid]  = p.bh1[tid];
      ((float*)(sm + ON_GH1))[tid]  = p.gh1[tid];
      ((float*)(sm + ON_BTH1))[tid] = p.bth1[tid];
    }
    if (tid < 64) ((float*)(sm + ON_BH2))[tid] = p.bh2[tid];
  }

  float* sRden = (float*)(sm + ON_RDEN);

  if (tid < 256) {
    int n = n0 + tid;
    float den = 1.f, nrm = 0.f;
    if (n < NNODES) {
      den = fmaxf(g_cnt[n], 1.f);
      float mvx = g_mv[2 * n] / den + 1e-8f;
      float mvy = g_mv[2 * n + 1] / den + 1e-8f;
      nrm = sqrtf(mvx * mvx + mvy * mvy);
    }
    sRden[tid] = 1.f / den;
    *(uint2*)(sm + ON_A2 + swb(tid, 64)) = make_uint2(h2pack(nrm, 0.f), 0u);
    uint2 z = make_uint2(0u, 0u);
#pragma unroll
    for (int gg = 1; gg < 16; ++gg)
      *(uint2*)(sm + ON_A2 + swb(tid, 64 + gg * 4)) = z;
  }
  __syncthreads();

  for (int i = tid; i < 256 * 32; i += 512) {
    int row = i >> 5, grp = i & 31;
    int n = n0 + row;
    float4 w = make_float4(0.f, 0.f, 0.f, 0.f);
    if (n < NNODES) {
      if (grp < 16) {
        w = *(const float4*)(p.x + n * 64 + grp * 4);
      } else {
        w = *(const float4*)(g_mh + n * 128 + (grp - 16) * 4);
        float rd = sRden[row];
        w.x *= rd; w.y *= rd; w.z *= rd; w.w *= rd;
      }
    }
    uint2 pk;
    pk.x = h2pack(w.x, w.y);
    pk.y = h2pack(w.z, w.w);
    *(uint2*)(sm + ON_A1 + swb(row, grp * 4)) = pk;
  }
  for (int i = tid; i < 256 * 16; i += 512) {
    int row = i >> 4, grp = i & 15;
    int n = n0 + row;
    float4 w = make_float4(0.f, 0.f, 0.f, 0.f);
    if (n < NNODES) {
      w = *(const float4*)(g_mh + n * 128 + 64 + grp * 4);
      float rd = sRden[row];
      w.x *= rd; w.y *= rd; w.z *= rd; w.w *= rd;
    }
    uint2 pk;
    pk.x = h2pack(w.x, w.y);
    pk.y = h2pack(w.z, w.w);
    *(uint2*)(sm + ON_A2 + swb(row, grp * 4)) = pk;
  }
  __syncthreads();

  const uint32_t smb = smem_u32(sm);
  const int g  = lane >> 2;
  const int q  = lane & 3;
  const int m0 = wid * 16;
  const int rA = m0 + g;
  const int rB = rA + 8;
  const float* cBH1 = (const float*)(sm + ON_BH1);
  const float* cGH1 = (const float*)(sm + ON_GH1);
  const float* cBT1 = (const float*)(sm + ON_BTH1);
  const float* cBH2 = (const float*)(sm + ON_BH2);

  float acc[16][4];
  warp_gemm<false, true>(smb + ON_A1, smb + ON_W1a, 0, 0, m0, lane, acc);
  warp_gemm<false, false>(smb + ON_A2, smb + ON_W1b, 0, 0, m0, lane, acc);
  {
    float sa = 0.f, s2a = 0.f, sb = 0.f, s2b = 0.f;
#pragma unroll
    for (int f = 0; f < 16; ++f) {
#pragma unroll
      for (int t = 0; t < 2; ++t) {
        int c = 8 * f + 2 * q + t;
        float bb = cBH1[c];
        float za = acc[f][t] + bb;
        float zb = acc[f][2 + t] + bb;
        acc[f][t] = za;
        acc[f][2 + t] = zb;
        sa += za; s2a = fmaf(za, za, s2a);
        sb += zb; s2b = fmaf(zb, zb, s2b);
      }
    }
#pragma unroll
    for (int m = 1; m < 4; m <<= 1) {
      sa  += __shfl_xor_sync(0xffffffffu, sa, m);
      s2a += __shfl_xor_sync(0xffffffffu, s2a, m);
      sb  += __shfl_xor_sync(0xffffffffu, sb, m);
      s2b += __shfl_xor_sync(0xffffffffu, s2b, m);
    }
    float mua = sa * (1.f / 128.f);
    float ria = rsqrtf(s2a * (1.f / 128.f) - mua * mua + 1e-5f);
    float mub = sb * (1.f / 128.f);
    float rib = rsqrtf(s2b * (1.f / 128.f) - mub * mub + 1e-5f);
#pragma unroll
    for (int f = 0; f < 16; ++f) {
      int c0 = 8 * f + 2 * q;
      float ha0 = softplus_f((acc[f][0] - mua) * ria * cGH1[c0] + cBT1[c0]);
      float ha1 = softplus_f((acc[f][1] - mua) * ria * cGH1[c0 + 1] + cBT1[c0 + 1]);
      float hb0 = softplus_f((acc[f][2] - mub) * rib * cGH1[c0] + cBT1[c0]);
      float hb1 = softplus_f((acc[f][3] - mub) * rib * cGH1[c0 + 1] + cBT1[c0 + 1]);
      *(uint32_t*)(sm + ON_A1 + swb(rA, c0)) = h2pack(ha0, ha1);
      *(uint32_t*)(sm + ON_A1 + swb(rB, c0)) = h2pack(hb0, hb1);
    }
  }
  __syncwarp();
  warp_gemm<false, true>(smb + ON_A1, smb + ON_W2, 0, 0, m0, lane, acc);
  {
    int nA = n0 + rA, nB = n0 + rB;
#pragma unroll
    for (int f = 0; f < 8; ++f) {
      int c0 = 8 * f + 2 * q;
      float b0 = cBH2[c0], b1 = cBH2[c0 + 1];
      if (nA < NNODES) {
        float2 xv = *(const float2*)(p.x + nA * 64 + c0);
        float2 o;
        o.x = xv.x + acc[f][0] + b0;
        o.y = xv.y + acc[f][1] + b1;
        *(float2*)(p.out + nA * 64 + c0) = o;
      }
      if (nB < NNODES) {
        float2 xv = *(const float2*)(p.x + nB * 64 + c0);
        float2 o;
        o.x = xv.x + acc[f][2] + b0;
        o.y = xv.y + acc[f][3] + b1;
        *(float2*)(p.out + nB * 64 + c0) = o;
      }
    }
  }
}

// ------------------------------ launch -------------------------------------
extern "C" void kernel_launch(void* const* d_in, const int* in_sizes, int n_in,
                              void* d_out, int out_size) {
  EdgeParams ep;
  ep.x    = (const float*)d_in[0];
  ep.pos  = (const float*)d_in[1];
  ep.vel  = (const float*)d_in[2];
  ep.We1  = (const float*)d_in[3];
  ep.be1  = (const float*)d_in[4];
  ep.ge1  = (const float*)d_in[5];
  ep.bte1 = (const float*)d_in[6];
  ep.We2  = (const float*)d_in[7];
  ep.be2  = (const float*)d_in[8];
  ep.We3  = (const float*)d_in[9];
  ep.be3  = (const float*)d_in[10];
  ep.Wv1  = (const float*)d_in[11];
  ep.bv1  = (const float*)d_in[12];
  ep.gv1  = (const float*)d_in[13];
  ep.btv1 = (const float*)d_in[14];
  ep.Wv2  = (const float*)d_in[15];
  ep.bv2  = (const float*)d_in[16];
  ep.ei   = (const int*)d_in[23];

  NodeParams np;
  np.x    = ep.x;
  np.Wh1  = (const float*)d_in[17];
  np.bh1  = (const float*)d_in[18];
  np.gh1  = (const float*)d_in[19];
  np.bth1 = (const float*)d_in[20];
  np.Wh2  = (const float*)d_in[21];
  np.bh2  = (const float*)d_in[22];
  np.out  = (float*)d_out;

  cudaFuncSetAttribute(edge_kernel, cudaFuncAttributeMaxDynamicSharedMemorySize,
                       EDGE_SMEM);
  cudaFuncSetAttribute(node_kernel, cudaFuncAttributeMaxDynamicSharedMemorySize,
                       NODE_SMEM);

  zero_kernel<<<(NNODES * H + 255) / 256, 256>>>();
  edge_kernel<<<148, 512, EDGE_SMEM>>>(ep);
  node_kernel<<<NODE_CTAS, 512, NODE_SMEM>>>(np);
}